// round 6
// baseline (speedup 1.0000x reference)
#include <cuda_runtime.h>
#include <cuda_bf16.h>
#include <mma.h>
#include <math.h>

using namespace nvcuda;

#define BATCH  2
#define SEQL   2048
#define DIM    1024
#define DINNER 2048
#define DSTATE 16
#define DTRANK 64
#define FFD    4096
#define MROWS  (BATCH*SEQL)   // 4096
#define RMS_EPS 1e-5f

// ---------------- scratch (static device arrays; no allocation) ----------------
__device__ float g_res [MROWS*DIM];
__device__ float g_norm[MROWS*DIM];
__device__ float g_xz  [MROWS*2*DINNER];
__device__ float g_xc  [MROWS*DINNER];
__device__ float g_xdbl[MROWS*96];
__device__ float g_delta[MROWS*DINNER];
__device__ float g_y   [MROWS*DINNER];
__device__ float g_h   [MROWS*DIM];
__device__ float g_u   [MROWS*2*FFD];
__device__ float g_v   [MROWS*FFD];

// ---------------- residual accumulate + RMSNorm ----------------
__global__ void resid_rms_kernel(const float* __restrict__ x,
                                 const float* __restrict__ w, int first) {
    int row = blockIdx.x;
    int t = threadIdx.x;
    float* res = g_res + (size_t)row*DIM;
    const float* hin = g_h + (size_t)row*DIM;
    const float* xin = x + (size_t)row*DIM;

    float v[4];
    float ss = 0.f;
#pragma unroll
    for (int i = 0; i < 4; i++) {
        int c = t + i*256;
        float r = first ? xin[c] : res[c] + hin[c];
        v[i] = r;
        res[c] = r;
        ss += r*r;
    }
    __shared__ float sred[8];
#pragma unroll
    for (int o = 16; o > 0; o >>= 1) ss += __shfl_xor_sync(0xffffffffu, ss, o);
    if ((t & 31) == 0) sred[t >> 5] = ss;
    __syncthreads();
    if (t < 32) {
        float s2 = (t < 8) ? sred[t] : 0.f;
#pragma unroll
        for (int o = 4; o > 0; o >>= 1) s2 += __shfl_xor_sync(0xffffffffu, s2, o);
        if (t == 0) sred[0] = s2;
    }
    __syncthreads();
    float scale = rsqrtf(sred[0]*(1.f/DIM) + RMS_EPS);
#pragma unroll
    for (int i = 0; i < 4; i++) {
        int c = t + i*256;
        g_norm[(size_t)row*DIM + c] = v[i]*scale*w[c];
    }
}

// ---------------- LayerNorm (in-place on g_h) ----------------
__global__ void layernorm_kernel(const float* __restrict__ w,
                                 const float* __restrict__ b) {
    int row = blockIdx.x;
    int t = threadIdx.x;
    float* hr = g_h + (size_t)row*DIM;
    float v[4];
    float s = 0.f, sq = 0.f;
#pragma unroll
    for (int i = 0; i < 4; i++) {
        int c = t + i*256;
        float r = hr[c];
        v[i] = r;
        s += r; sq += r*r;
    }
    __shared__ float sredA[8], sredB[8];
#pragma unroll
    for (int o = 16; o > 0; o >>= 1) {
        s  += __shfl_xor_sync(0xffffffffu, s, o);
        sq += __shfl_xor_sync(0xffffffffu, sq, o);
    }
    if ((t & 31) == 0) { sredA[t >> 5] = s; sredB[t >> 5] = sq; }
    __syncthreads();
    if (t < 32) {
        float s2 = (t < 8) ? sredA[t] : 0.f;
        float q2 = (t < 8) ? sredB[t] : 0.f;
#pragma unroll
        for (int o = 4; o > 0; o >>= 1) {
            s2 += __shfl_xor_sync(0xffffffffu, s2, o);
            q2 += __shfl_xor_sync(0xffffffffu, q2, o);
        }
        if (t == 0) { sredA[0] = s2; sredB[0] = q2; }
    }
    __syncthreads();
    float mu  = sredA[0]*(1.f/DIM);
    float var = sredB[0]*(1.f/DIM) - mu*mu;
    float inv = rsqrtf(var + RMS_EPS);
#pragma unroll
    for (int i = 0; i < 4; i++) {
        int c = t + i*256;
        hr[c] = (v[i]-mu)*inv*w[c] + b[c];
    }
}

// ---------------- bf16x3 tensor-core GEMM ----------------
// C[M,N] = A[M,K](lda) * W[N,K]^T (+bias)(+softplus)
// Split each fp32 input x = hi + lo (bf16 each); acc += Ah*Bh + Ah*Bl + Al*Bh in fp32.
// BM=128, BN=64, BK=16; 128 threads = 4 warps, warp tile 64x32 (4x2 wmma tiles).
// Smem double-buffered: 1 barrier per k-tile; split+STS overlap the mma block.
// Call-site guarantees: M%128==0, N%16==0, K%16==0.
#define GPAD 24   // bf16 plane ld (16 + 8); keeps ldm%8==0 and 8B vector stores

__device__ __forceinline__ void split_store4(__nv_bfloat16* hi, __nv_bfloat16* lo,
                                             float4 v) {
    union { uint2 u; __nv_bfloat16 b[4]; } ph, pl;
    float f[4] = {v.x, v.y, v.z, v.w};
#pragma unroll
    for (int j = 0; j < 4; j++) {
        __nv_bfloat16 h = __float2bfloat16(f[j]);
        ph.b[j] = h;
        pl.b[j] = __float2bfloat16(f[j] - __bfloat162float(h));
    }
    *(uint2*)hi = ph.u;
    *(uint2*)lo = pl.u;
}

__global__ void __launch_bounds__(128, 3)
gemm_bf16x3_kernel(const float* __restrict__ A, const float* __restrict__ W,
                   const float* __restrict__ bias, float* __restrict__ C,
                   int M, int N, int K, int lda, int mode) {
    __shared__ __align__(128) union {
        struct {
            __nv_bfloat16 Ah[2][128][GPAD];
            __nv_bfloat16 Al[2][128][GPAD];
            __nv_bfloat16 Bh[2][64][GPAD];
            __nv_bfloat16 Bl[2][64][GPAD];
        } m;
        float stage[128][68];
    } sm;

    const int tid = threadIdx.x;
    const int lr  = tid >> 2;        // 0..31
    const int lk  = (tid & 3) * 4;   // 0,4,8,12
    const int wid = tid >> 5;
    const int m0  = (wid >> 1) * 64; // warp m offset within tile
    const int n0  = (wid & 1) * 32;  // warp n offset within tile
    const int bm  = blockIdx.y * 128;
    const int bn  = blockIdx.x * 64;

    wmma::fragment<wmma::accumulator, 16, 16, 16, float> acc[4][2];
#pragma unroll
    for (int i = 0; i < 4; i++)
#pragma unroll
        for (int j = 0; j < 2; j++) wmma::fill_fragment(acc[i][j], 0.f);

    float4 aR[4], bR[2];
    // prologue: load k-tile 0 into registers, commit to buffer 0
#pragma unroll
    for (int i = 0; i < 4; i++) {
        int row = lr + 32*i;
        aR[i] = *(const float4*)&A[(size_t)(bm+row)*lda + lk];
    }
#pragma unroll
    for (int i = 0; i < 2; i++) {
        int nrow = bn + lr + 32*i;
        bR[i] = make_float4(0.f,0.f,0.f,0.f);
        if (nrow < N) bR[i] = *(const float4*)&W[(size_t)nrow*K + lk];
    }
#pragma unroll
    for (int i = 0; i < 4; i++) {
        int row = lr + 32*i;
        split_store4(&sm.m.Ah[0][row][lk], &sm.m.Al[0][row][lk], aR[i]);
    }
#pragma unroll
    for (int i = 0; i < 2; i++) {
        int row = lr + 32*i;
        split_store4(&sm.m.Bh[0][row][lk], &sm.m.Bl[0][row][lk], bR[i]);
    }
    __syncthreads();

    const int ntiles = K >> 4;
    for (int t = 0; t < ntiles; t++) {
        const int cur = t & 1, nxt = cur ^ 1;

        // prefetch next k-tile into registers (LDGs issue before mma block)
        if (t + 1 < ntiles) {
            int kn = (t+1) << 4;
#pragma unroll
            for (int i = 0; i < 4; i++) {
                int row = lr + 32*i;
                aR[i] = *(const float4*)&A[(size_t)(bm+row)*lda + kn + lk];
            }
#pragma unroll
            for (int i = 0; i < 2; i++) {
                int nrow = bn + lr + 32*i;
                bR[i] = make_float4(0.f,0.f,0.f,0.f);
                if (nrow < N) bR[i] = *(const float4*)&W[(size_t)nrow*K + kn + lk];
            }
        }

        // fragments + 3-plane mma from current buffer
        wmma::fragment<wmma::matrix_a, 16, 16, 16, __nv_bfloat16, wmma::row_major> ah[4], al[4];
        wmma::fragment<wmma::matrix_b, 16, 16, 16, __nv_bfloat16, wmma::col_major> bh[2], bl[2];
#pragma unroll
        for (int i = 0; i < 4; i++) {
            wmma::load_matrix_sync(ah[i], &sm.m.Ah[cur][m0 + 16*i][0], GPAD);
            wmma::load_matrix_sync(al[i], &sm.m.Al[cur][m0 + 16*i][0], GPAD);
        }
#pragma unroll
        for (int j = 0; j < 2; j++) {
            wmma::load_matrix_sync(bh[j], &sm.m.Bh[cur][n0 + 16*j][0], GPAD);
            wmma::load_matrix_sync(bl[j], &sm.m.Bl[cur][n0 + 16*j][0], GPAD);
        }
#pragma unroll
        for (int i = 0; i < 4; i++)
#pragma unroll
            for (int j = 0; j < 2; j++) {
                wmma::mma_sync(acc[i][j], ah[i], bh[j], acc[i][j]);
                wmma::mma_sync(acc[i][j], ah[i], bl[j], acc[i][j]);
                wmma::mma_sync(acc[i][j], al[i], bh[j], acc[i][j]);
            }

        // split + store prefetched tile into the other buffer; 1 barrier/tile
        if (t + 1 < ntiles) {
#pragma unroll
            for (int i = 0; i < 4; i++) {
                int row = lr + 32*i;
                split_store4(&sm.m.Ah[nxt][row][lk], &sm.m.Al[nxt][row][lk], aR[i]);
            }
#pragma unroll
            for (int i = 0; i < 2; i++) {
                int row = lr + 32*i;
                split_store4(&sm.m.Bh[nxt][row][lk], &sm.m.Bl[nxt][row][lk], bR[i]);
            }
            __syncthreads();
        }
    }

    // all warps done reading mainloop smem before the union is reused as stage
    __syncthreads();

    // epilogue: stage accs in smem, then elementwise + vectorized stores
#pragma unroll
    for (int i = 0; i < 4; i++)
#pragma unroll
        for (int j = 0; j < 2; j++)
            wmma::store_matrix_sync(&sm.stage[m0 + 16*i][n0 + 16*j], acc[i][j],
                                    68, wmma::mem_row_major);
    __syncthreads();

    const int col = (tid & 15) * 4;       // 0..60
    const int r0  = tid >> 4;             // 0..7
    int n = bn + col;
    if (n < N) {                           // N%16==0, col%4==0 -> n+3 < N
        float4 bb = make_float4(0.f,0.f,0.f,0.f);
        if (mode >= 1) bb = *(const float4*)&bias[n];
#pragma unroll
        for (int rr = 0; rr < 16; rr++) {
            int row = r0 + rr*8;
            float4 vv = *(float4*)&sm.stage[row][col];
            if (mode >= 1) { vv.x += bb.x; vv.y += bb.y; vv.z += bb.z; vv.w += bb.w; }
            if (mode == 2) {
                vv.x = fmaxf(vv.x,0.f) + log1pf(expf(-fabsf(vv.x)));
                vv.y = fmaxf(vv.y,0.f) + log1pf(expf(-fabsf(vv.y)));
                vv.z = fmaxf(vv.z,0.f) + log1pf(expf(-fabsf(vv.z)));
                vv.w = fmaxf(vv.w,0.f) + log1pf(expf(-fabsf(vv.w)));
            }
            *(float4*)&C[(size_t)(bm+row)*N + n] = vv;
        }
    }
}

// ---------------- depthwise causal conv1d + bias + SiLU ----------------
__global__ void conv_silu_kernel(const float* __restrict__ cw,
                                 const float* __restrict__ cb) {
    int idx = blockIdx.x*blockDim.x + threadIdx.x;      // [bl, d]
    int d  = idx & (DINNER-1);
    int bl = idx >> 11;
    int l  = bl & (SEQL-1);
    float acc = cb[d];
    const float* xin = g_xz + (size_t)bl*(2*DINNER) + d;  // x half
#pragma unroll
    for (int j = 0; j < 4; j++) {
        int off = (j - 3) * (2*DINNER);    // signed offset: rows back in time
        if (l - 3 + j >= 0) acc = fmaf(cw[d*4 + j], xin[off], acc);
    }
    g_xc[idx] = acc / (1.f + expf(-acc));
}

// ---------------- selective scan + fused silu(z) gate ----------------
// 2 channels/warp, 16 states per half-warp, butterfly reduce over states
__global__ void scan_kernel(const float* __restrict__ A_log,
                            const float* __restrict__ Dp) {
    int w    = (blockIdx.x*blockDim.x + threadIdx.x) >> 5;
    int lane = threadIdx.x & 31;
    int b    = w >> 10;           // /1024
    int pair = w & 1023;
    int d    = pair*2 + (lane >> 4);
    int n    = lane & 15;

    float a  = -expf(A_log[d*DSTATE + n]);
    float Dd = Dp[d];

    const float* dl = g_delta + (size_t)b*SEQL*DINNER + d;
    const float* ul = g_xc    + (size_t)b*SEQL*DINNER + d;
    const float* bc = g_xdbl  + (size_t)b*SEQL*96;
    const float* zl = g_xz    + (size_t)b*SEQL*(2*DINNER) + DINNER + d;
    float*       yp = g_y     + (size_t)b*SEQL*DINNER + d;

    float h = 0.f;
    float dt = dl[0], u = ul[0], z = zl[0];
    float Bt = bc[64 + n], Ct = bc[80 + n];
    for (int l = 0; l < SEQL; l++) {
        float dt_c = dt, u_c = u, B_c = Bt, C_c = Ct, z_c = z;
        if (l + 1 < SEQL) {
            size_t r = (size_t)(l+1);
            dt = dl[r*DINNER];  u = ul[r*DINNER];
            Bt = bc[r*96 + 64 + n];  Ct = bc[r*96 + 80 + n];
            z  = zl[r*(2*DINNER)];
        }
        float dA = expf(dt_c * a);
        h = fmaf(dA, h, dt_c*u_c*B_c);
        float p = h * C_c;
        p += __shfl_xor_sync(0xffffffffu, p, 1);
        p += __shfl_xor_sync(0xffffffffu, p, 2);
        p += __shfl_xor_sync(0xffffffffu, p, 4);
        p += __shfl_xor_sync(0xffffffffu, p, 8);
        if (n == 0) {
            float sg = z_c / (1.f + expf(-z_c));
            yp[(size_t)l*DINNER] = fmaf(u_c, Dd, p) * sg;
        }
    }
}

// ---------------- GeGLU (exact gelu) ----------------
__global__ void geglu_kernel() {
    int idx = blockIdx.x*blockDim.x + threadIdx.x;     // [m, f]
    int f = idx & (FFD-1);
    int m = idx >> 12;
    float av = g_u[(size_t)m*2*FFD + f];
    float g  = g_u[(size_t)m*2*FFD + FFD + f];
    float ge = 0.5f * g * (1.f + erff(g * 0.70710678118654752f));
    g_v[idx] = av * ge;
}

// ---------------- host launcher ----------------
extern "C" void kernel_launch(void* const* d_in, const int* in_sizes, int n_in,
                              void* d_out, int out_size) {
    const float* x      = (const float*)d_in[0];
    const float* in_w   = (const float*)d_in[1];
    const float* conv_w = (const float*)d_in[2];
    const float* conv_b = (const float*)d_in[3];
    const float* xp_w   = (const float*)d_in[4];
    const float* dt_w   = (const float*)d_in[5];
    const float* dt_b   = (const float*)d_in[6];
    const float* A_log  = (const float*)d_in[7];
    const float* Dp     = (const float*)d_in[8];
    const float* out_w  = (const float*)d_in[9];
    const float* rms_w  = (const float*)d_in[10];
    const float* ln_w   = (const float*)d_in[11];
    const float* ln_b   = (const float*)d_in[12];
    const float* ff_w1  = (const float*)d_in[13];
    const float* ff_b1  = (const float*)d_in[14];
    const float* ff_w2  = (const float*)d_in[15];
    const float* ff_b2  = (const float*)d_in[16];
    float* out = (float*)d_out;

    void *pNorm, *pXz, *pXc, *pXdbl, *pDelta, *pY, *pH, *pU, *pV;
    cudaGetSymbolAddress(&pNorm, g_norm);
    cudaGetSymbolAddress(&pXz,   g_xz);
    cudaGetSymbolAddress(&pXc,   g_xc);
    cudaGetSymbolAddress(&pXdbl, g_xdbl);
    cudaGetSymbolAddress(&pDelta,g_delta);
    cudaGetSymbolAddress(&pY,    g_y);
    cudaGetSymbolAddress(&pH,    g_h);
    cudaGetSymbolAddress(&pU,    g_u);
    cudaGetSymbolAddress(&pV,    g_v);

    const int EW_BLOCKS = (MROWS*DINNER)/256;  // 32768

    for (int i = 0; i < 2; i++) {
        resid_rms_kernel<<<MROWS, 256>>>(x, rms_w + (size_t)i*DIM, i == 0 ? 1 : 0);

        // in_proj: [4096,1024] x [4096,1024]^T -> xz [4096,4096]
        gemm_bf16x3_kernel<<<dim3(64,32), 128>>>((const float*)pNorm,
            in_w + (size_t)i*4096*DIM, nullptr, (float*)pXz,
            MROWS, 2*DINNER, DIM, DIM, 0);

        conv_silu_kernel<<<EW_BLOCKS, 256>>>(conv_w + (size_t)i*DINNER*4,
                                             conv_b + (size_t)i*DINNER);

        // x_proj: [4096,2048] x [96,2048]^T -> x_dbl [4096,96]
        gemm_bf16x3_kernel<<<dim3(2,32), 128>>>((const float*)pXc,
            xp_w + (size_t)i*96*DINNER, nullptr, (float*)pXdbl,
            MROWS, 96, DINNER, DINNER, 0);

        // dt_proj + softplus: [4096,64](lda=96) x [2048,64]^T -> delta [4096,2048]
        gemm_bf16x3_kernel<<<dim3(32,32), 128>>>((const float*)pXdbl,
            dt_w + (size_t)i*DINNER*DTRANK, dt_b + (size_t)i*DINNER, (float*)pDelta,
            MROWS, DINNER, DTRANK, 96, 2);

        scan_kernel<<<256, 256>>>(A_log + (size_t)i*DINNER*DSTATE,
                                  Dp + (size_t)i*DINNER);

        // out_proj: [4096,2048] x [1024,2048]^T -> h [4096,1024]
        gemm_bf16x3_kernel<<<dim3(16,32), 128>>>((const float*)pY,
            out_w + (size_t)i*DIM*DINNER, nullptr, (float*)pH,
            MROWS, DIM, DINNER, DINNER, 0);

        layernorm_kernel<<<MROWS, 256>>>(ln_w + (size_t)i*DIM, ln_b + (size_t)i*DIM);
    }

    // ff1: [4096,1024] x [8192,1024]^T + b -> u [4096,8192]
    gemm_bf16x3_kernel<<<dim3(128,32), 128>>>((const float*)pH, ff_w1, ff_b1,
                                              (float*)pU, MROWS, 2*FFD, DIM, DIM, 1);
    geglu_kernel<<<(MROWS*FFD)/256, 256>>>();
    // ff2: [4096,4096] x [1024,4096]^T + b -> out [4096,1024]
    gemm_bf16x3_kernel<<<dim3(16,32), 128>>>((const float*)pV, ff_w2, ff_b2, out,
                                             MROWS, DIM, FFD, FFD, 1);
}